// round 9
// baseline (speedup 1.0000x reference)
#include <cuda_runtime.h>
#include <cuda_fp16.h>
#include <cstdint>

// ---------------------------------------------------------------------------
// HDSLinear (sm_103, 2:4 SPARSE HMMA path):
//   out[M,N] = x[M,K] @ (W*mask)[N,K]^T + bias,  M=16384, N=K=4096
// Computed as out^T = Wm @ x^T with mma.sp (A = compressed Wm, 2:4 along K).
// gemm: CTA tile 256(N) x 128(M), 512 threads / 16 warps (8Nx2M of 32x64),
//       K-stage depth 64 (2 k-chunks), 3-stage cp.async.cg pipeline,
//       mma.sp::ordered_metadata.m16n8k32, 16 warps/SM,
//       smem-transpose epilogue with coalesced stores + bias.
// ---------------------------------------------------------------------------

#define EPSV 1e-10f

constexpr int KD = 4096;
constexpr int ND = 4096;
constexpr int NKT = KD / 32;             // 128 k-chunks of 32
constexpr int NKT2 = NKT / 2;            // 64 stages of K=64
constexpr int A_CH = 8192;               // compressed W bytes / k-chunk (256 rows)
constexpr int E_CH = 2048;               // metadata bytes / k-chunk
constexpr int B_CH = 8192;               // x^T bytes / k-chunk (128 cols)
constexpr int A_ST = 2 * A_CH;           // 16384
constexpr int E_ST = 2 * E_CH;           // 4096
constexpr int B_ST = 2 * B_CH;           // 16384
constexpr int STAGE_B = A_ST + E_ST + B_ST;   // 36864
constexpr int SMEM_GEMM = 3 * STAGE_B;        // 110592

// fragment panels
__device__ uint4    g_xp[128ull * NKT * 512];   // [mb][kt][jm(16)*32+lane]
__device__ uint4    g_wa[16ull * NKT * 512];    // [nbBig][kt][jn(16)*32+lane]
__device__ uint32_t g_we[16ull * NKT * 512];    // metadata, same indexing

// ----------------------------- helpers ------------------------------------
__device__ __forceinline__ uint32_t packh2(float lo, float hi) {
    __half2 h = __floats2half2_rn(lo, hi);
    return *(uint32_t*)&h;
}
__device__ __forceinline__ uint32_t smem_u32(const void* p) {
    uint32_t a;
    asm("{ .reg .u64 t; cvta.to.shared.u64 t, %1; cvt.u32.u64 %0, t; }"
        : "=r"(a) : "l"(p));
    return a;
}

#define CP_ASYNC_16(dst, src) \
    asm volatile("cp.async.cg.shared.global [%0], [%1], 16;" \
                 :: "r"(dst), "l"(src) : "memory")
#define CP_COMMIT() asm volatile("cp.async.commit_group;" ::: "memory")
#define CP_WAIT1()  asm volatile("cp.async.wait_group 1;"  ::: "memory")
#define CP_WAIT0()  asm volatile("cp.async.wait_group 0;"  ::: "memory")

// -------------------- pack_x: x^T B-fragments ------------------------------
// grid (NKT, M/128), 256 threads.
__global__ void __launch_bounds__(256) pack_x(const float* __restrict__ x)
{
    __shared__ float s[128 * 36];
    const int mb = blockIdx.y, kt = blockIdx.x, tid = threadIdx.x;
    const float* xb = x + ((size_t)mb * 128) * KD + kt * 32;

#pragma unroll
    for (int i = 0; i < 4; i++) {
        int idx = i * 256 + tid;
        int row = idx >> 3;
        int c4  = idx & 7;
        float4 v = __ldg((const float4*)(xb + (size_t)row * KD + c4 * 4));
        float* d = &s[row * 36 + c4 * 4];
        d[0] = v.x; d[1] = v.y; d[2] = v.z; d[3] = v.w;
    }
    __syncthreads();

    uint4* out = g_xp + ((size_t)mb * NKT + kt) * 512;
#pragma unroll
    for (int i = 0; i < 2; i++) {
        int o  = i * 256 + tid;             // 512 fragments
        int jm = o >> 5, ln = o & 31;
        int g = ln >> 2, t = ln & 3;
        const float* r = &s[(jm * 8 + g) * 36 + 2 * t];
        uint4 v;
        v.x = packh2(r[0],  r[1]);
        v.y = packh2(r[8],  r[9]);
        v.z = packh2(r[16], r[17]);
        v.w = packh2(r[24], r[25]);
        out[o] = v;
    }
}

// -------------------- pack_w: mask + compress + meta ------------------------
// grid (NKT, ND/128), 256 threads. Output into 256-row big panels.
__global__ void __launch_bounds__(256) pack_w(
    const float* __restrict__ w,
    const float* __restrict__ sc,
    const float* __restrict__ nu)
{
    __shared__ __half comp[128 * 18];      // compressed halves, stride 18
    __shared__ uint8_t metb[128 * 8];      // nibble per (row, group)
    const int nb128 = blockIdx.y, kt = blockIdx.x, tid = threadIdx.x;
    const size_t base = ((size_t)nb128 * 128) * KD + kt * 32;

#pragma unroll
    for (int i = 0; i < 4; i++) {
        int idx = i * 256 + tid;            // 1024 chunks = (row, group)
        int row = idx >> 3;
        int grp = idx & 7;
        size_t off = base + (size_t)row * KD + grp * 4;
        float4 w4 = __ldg((const float4*)(w + off));
        float4 s4 = __ldg((const float4*)(sc + off));
        float4 u4 = __ldg((const float4*)(nu + off));

        float sv[4] = {s4.x, s4.y, s4.z, s4.w};
        float uv[4] = {u4.x, u4.y, u4.z, u4.w};
        float y[4];
#pragma unroll
        for (int j = 0; j < 4; j++)
            y[j] = sv[j] - logf(-logf(uv[j] + EPSV) + EPSV);

        // top-2, first occurrence wins on ties (jax top_k semantics)
        int i1 = 0;
#pragma unroll
        for (int j = 1; j < 4; j++) if (y[j] > y[i1]) i1 = j;
        int i2 = (i1 == 0) ? 1 : 0;
#pragma unroll
        for (int j = 0; j < 4; j++)
            if (j != i1 && j != i2 && y[j] > y[i2]) i2 = j;

        int lo = min(i1, i2), hi = max(i1, i2);
        float wv[4] = {w4.x, w4.y, w4.z, w4.w};
        *(__half2*)&comp[row * 18 + grp * 2] =
            __floats2half2_rn(wv[lo], wv[hi]);
        metb[row * 8 + grp] = (uint8_t)(lo | (hi << 2));
    }
    __syncthreads();

    // A fragments + metadata into big-panel layout
    {
        int jn = tid >> 5, ln = tid & 31;
        int g = ln >> 2, t = ln & 3;
        int r0 = jn * 16 + g, r8 = r0 + 8;
        uint4 v;
        v.x = *(const uint32_t*)&comp[r0 * 18 + 2 * t];
        v.y = *(const uint32_t*)&comp[r8 * 18 + 2 * t];
        v.z = *(const uint32_t*)&comp[r0 * 18 + 2 * t + 8];
        v.w = *(const uint32_t*)&comp[r8 * 18 + 2 * t + 8];

        int nbBig = nb128 >> 1;
        int joff  = (nb128 & 1) * 8;
        size_t slot = (((size_t)nbBig * NKT + kt) * 16 + joff + jn) * 32 + ln;
        g_wa[slot] = v;

        // metadata: lane%4==0 -> k-groups 0..3, ==1 -> 4..7; low16=row g,
        // high16=row g+8; nibble = idx0 | idx1<<2 (ascending).
        uint32_t e = 0;
        if (t < 2) {
            int gb = t * 4;
            uint32_t lo16 = (uint32_t)metb[r0 * 8 + gb]
                          | ((uint32_t)metb[r0 * 8 + gb + 1] << 4)
                          | ((uint32_t)metb[r0 * 8 + gb + 2] << 8)
                          | ((uint32_t)metb[r0 * 8 + gb + 3] << 12);
            uint32_t hi16 = (uint32_t)metb[r8 * 8 + gb]
                          | ((uint32_t)metb[r8 * 8 + gb + 1] << 4)
                          | ((uint32_t)metb[r8 * 8 + gb + 2] << 8)
                          | ((uint32_t)metb[r8 * 8 + gb + 3] << 12);
            e = lo16 | (hi16 << 16);
        }
        g_we[slot] = e;
    }
}

// ------------------------------- GEMM --------------------------------------
// out^T tile: 256 N-rows x 128 M-cols. 16 warps: wn=warp>>1 (8 tiles of 32N),
// wm=warp&1 (64M). Stage covers K=64 (2 chunks); 64 iterations.
__global__ void __launch_bounds__(512, 1) gemm_kernel(
    const float* __restrict__ bias,
    float* __restrict__ C)
{
    extern __shared__ char smem[];
    const uint32_t sb = smem_u32(smem);
    const int tid  = threadIdx.x;
    const int warp = tid >> 5;
    const int lane = tid & 31;
    const int wn   = warp >> 1;   // 0..7 -> 32 N rows
    const int wm   = warp & 1;    // 0..1 -> 64 M cols
    const int g    = lane >> 2;
    const int t    = lane & 3;

    const int nb = blockIdx.x;    // 0..15 (256-row big panel)
    const int mb = blockIdx.y;

    const char* pA = (const char*)(g_wa + (size_t)nb * NKT * 512);
    const char* pE = (const char*)(g_we + (size_t)nb * NKT * 512);
    const char* pB = (const char*)(g_xp + (size_t)mb * NKT * 512);

    float acc[2][8][4];
#pragma unroll
    for (int at = 0; at < 2; at++)
#pragma unroll
        for (int bt = 0; bt < 8; bt++)
#pragma unroll
            for (int i = 0; i < 4; i++) acc[at][bt][i] = 0.0f;

    // issue one K=64 stage: A 16KB (2/thr), E 4KB (tid<256), B 16KB (2/thr)
#define ISSUE(st, k2) do {                                                    \
    uint32_t _d = sb + (st) * STAGE_B;                                        \
    size_t _ka = (size_t)(k2) * A_ST;                                         \
    size_t _kb = (size_t)(k2) * B_ST;                                         \
    _Pragma("unroll")                                                         \
    for (int _j = 0; _j < 2; _j++) {                                          \
        int _i = _j * 512 + tid;                                              \
        CP_ASYNC_16(_d + _i * 16, pA + _ka + _i * 16);                        \
        CP_ASYNC_16(_d + A_ST + E_ST + _i * 16, pB + _kb + _i * 16);          \
    }                                                                         \
    if (tid < 256)                                                            \
        CP_ASYNC_16(_d + A_ST + tid * 16,                                     \
                    pE + (size_t)(k2) * E_ST + tid * 16);                     \
    CP_COMMIT();                                                              \
} while (0)

    ISSUE(0, 0);
    ISSUE(1, 1);

    int cur = 0;
    for (int k2 = 0; k2 < NKT2; k2++) {
        CP_WAIT1();
        __syncthreads();
        if (k2 + 2 < NKT2) {
            int nst = cur + 2; if (nst >= 3) nst -= 3;
            ISSUE(nst, k2 + 2);
        }

        const char* st = smem + cur * STAGE_B;
#pragma unroll
        for (int kc = 0; kc < 2; kc++) {
            const uint4*    As = (const uint4*)(st + kc * A_CH);
            const uint32_t* Es = (const uint32_t*)(st + A_ST + kc * E_CH);
            const uint4*    Bs = (const uint4*)(st + A_ST + E_ST + kc * B_CH);

            uint4 af[2];
            uint32_t ea[2];
#pragma unroll
            for (int at = 0; at < 2; at++) {
                af[at] = As[(wn * 2 + at) * 32 + lane];
                ea[at] = Es[(wn * 2 + at) * 32 + lane];
            }
#pragma unroll
            for (int bt = 0; bt < 8; bt++) {
                uint4 bf = Bs[(wm * 8 + bt) * 32 + lane];
#pragma unroll
                for (int at = 0; at < 2; at++) {
                    asm volatile(
                        "mma.sp::ordered_metadata.sync.aligned.m16n8k32."
                        "row.col.f32.f16.f16.f32 "
                        "{%0,%1,%2,%3}, {%4,%5,%6,%7}, {%8,%9,%10,%11}, "
                        "{%0,%1,%2,%3}, %12, 0x0;"
                        : "+f"(acc[at][bt][0]), "+f"(acc[at][bt][1]),
                          "+f"(acc[at][bt][2]), "+f"(acc[at][bt][3])
                        : "r"(af[at].x), "r"(af[at].y),
                          "r"(af[at].z), "r"(af[at].w),
                          "r"(bf.x), "r"(bf.y), "r"(bf.z), "r"(bf.w),
                          "r"(ea[at]));
                }
            }
        }
        if (++cur == 3) cur = 0;
    }
#undef ISSUE

    // ---- epilogue: per-warp smem transpose, coalesced stores + bias ----
    CP_WAIT0();
    __syncthreads();   // wbuf regions overlap stage data other warps may read

    const long n0 = (long)nb * 256 + wn * 32;
    const float bv = __ldg(&bias[n0 + lane]);
    float* wbuf = (float*)(smem + warp * 4224);   // 32 x 33 floats

#pragma unroll
    for (int p = 0; p < 2; p++) {
#pragma unroll
        for (int at = 0; at < 2; at++) {
#pragma unroll
            for (int b2 = 0; b2 < 4; b2++) {
                int bt = p * 4 + b2;
                int mrow = b2 * 8 + 2 * t;
                int ncol = at * 16 + g;
                wbuf[mrow * 33 + ncol]           = acc[at][bt][0];
                wbuf[(mrow + 1) * 33 + ncol]     = acc[at][bt][1];
                wbuf[mrow * 33 + ncol + 8]       = acc[at][bt][2];
                wbuf[(mrow + 1) * 33 + ncol + 8] = acc[at][bt][3];
            }
        }
        __syncwarp();
        long gmr = (long)mb * 128 + wm * 64 + p * 32;
#pragma unroll
        for (int m = 0; m < 32; m++) {
            C[(gmr + m) * (long)ND + n0 + lane] = wbuf[m * 33 + lane] + bv;
        }
        __syncwarp();
    }
}

// ----------------------------- launch --------------------------------------
extern "C" void kernel_launch(void* const* d_in, const int* in_sizes, int n_in,
                              void* d_out, int out_size)
{
    const float* x      = (const float*)d_in[0];
    const float* weight = (const float*)d_in[1];
    const float* bias   = (const float*)d_in[2];
    const float* scores = (const float*)d_in[3];
    const float* noise  = (const float*)d_in[4];
    float* out = (float*)d_out;

    const int M = in_sizes[0] / KD;   // 16384

    cudaFuncSetAttribute(gemm_kernel,
                         cudaFuncAttributeMaxDynamicSharedMemorySize, SMEM_GEMM);

    pack_x<<<dim3(NKT, M / 128), 256>>>(x);
    pack_w<<<dim3(NKT, ND / 128), 256>>>(weight, scores, noise);

    dim3 grid(ND / 256, M / 128);     // (nb=16, mb=128), x-fastest shares x-panel
    gemm_kernel<<<grid, 512, SMEM_GEMM>>>(bias, out);
}

// round 11
// speedup vs baseline: 1.0621x; 1.0621x over previous
#include <cuda_runtime.h>
#include <cuda_fp16.h>
#include <cstdint>

// ---------------------------------------------------------------------------
// HDSLinear (sm_103, 2:4 SPARSE HMMA path):
//   out[M,N] = x[M,K] @ (W*mask)[N,K]^T + bias,  M=16384, N=K=4096
// Computed as out^T = Wm @ x^T with mma.sp (A = compressed Wm, 2:4 along K).
// pack_all: fused x-repack + gumbel-mask W-compress (one wave train).
// gemm: CTA tile 128(N) x 128(M), K-stage depth 64 (2 k-chunks), 4-stage
//       cp.async.cg pipeline (distance 3), 8 warps (4Nx2M of 32x64),
//       mma.sp::ordered_metadata.m16n8k32, 2 CTAs/SM,
//       smem-transpose epilogue with coalesced stores + bias.
// ---------------------------------------------------------------------------

#define EPSV 1e-10f

constexpr int KD = 4096;
constexpr int ND = 4096;
constexpr int NKT = KD / 32;             // 128 k-chunks of 32
constexpr int NKT2 = NKT / 2;            // 64 stages of K=64
constexpr int A_CH = 4096;               // compressed W bytes per k-chunk
constexpr int E_CH = 1024;               // metadata bytes per k-chunk
constexpr int B_CH = 8192;               // x^T bytes per k-chunk
constexpr int A_ST = 2 * A_CH;           // 8192
constexpr int E_ST = 2 * E_CH;           // 2048
constexpr int B_ST = 2 * B_CH;           // 16384
constexpr int STAGE_B = A_ST + E_ST + B_ST;   // 26624
constexpr int SMEM_GEMM = 4 * STAGE_B;        // 106496 (2 CTAs/SM: 208KB)

// fragment panels
__device__ uint4    g_xp[128ull * NKT * 512];   // [mb][kt][jm(16)*32+lane]
__device__ uint4    g_wa[32ull * NKT * 256];    // [nb][kt][jn(8)*32+lane]
__device__ uint32_t g_we[32ull * NKT * 256];    // metadata, same indexing

// ----------------------------- helpers ------------------------------------
__device__ __forceinline__ uint32_t packh2(float lo, float hi) {
    __half2 h = __floats2half2_rn(lo, hi);
    return *(uint32_t*)&h;
}
__device__ __forceinline__ uint32_t smem_u32(const void* p) {
    uint32_t a;
    asm("{ .reg .u64 t; cvta.to.shared.u64 t, %1; cvt.u32.u64 %0, t; }"
        : "=r"(a) : "l"(p));
    return a;
}

#define CP_ASYNC_16(dst, src) \
    asm volatile("cp.async.cg.shared.global [%0], [%1], 16;" \
                 :: "r"(dst), "l"(src) : "memory")
#define CP_COMMIT() asm volatile("cp.async.commit_group;" ::: "memory")
#define CP_WAIT2()  asm volatile("cp.async.wait_group 2;"  ::: "memory")
#define CP_WAIT0()  asm volatile("cp.async.wait_group 0;"  ::: "memory")

// -------------------- pack_all: fused x-repack + W mask/compress ------------
// grid (NKT, 128 + 32), 256 threads.
//   blockIdx.y <  128 : pack x panel mb = blockIdx.y
//   blockIdx.y >= 128 : pack W panel nb = blockIdx.y - 128 (gumbel top-2-of-4)
__global__ void __launch_bounds__(256) pack_all(
    const float* __restrict__ x,
    const float* __restrict__ w,
    const float* __restrict__ sc,
    const float* __restrict__ nu)
{
    __shared__ char smraw[128 * 36 * 4];   // 18432 B, unioned
    const int kt = blockIdx.x, tid = threadIdx.x;

    if (blockIdx.y < 128) {
        // ---------------- x path ----------------
        float* s = (float*)smraw;          // 128 x 36
        const int mb = blockIdx.y;
        const float* xb = x + ((size_t)mb * 128) * KD + kt * 32;

#pragma unroll
        for (int i = 0; i < 4; i++) {
            int idx = i * 256 + tid;
            int row = idx >> 3;
            int c4  = idx & 7;
            float4 v = __ldg((const float4*)(xb + (size_t)row * KD + c4 * 4));
            float* d = &s[row * 36 + c4 * 4];
            d[0] = v.x; d[1] = v.y; d[2] = v.z; d[3] = v.w;
        }
        __syncthreads();

        uint4* out = g_xp + ((size_t)mb * NKT + kt) * 512;
#pragma unroll
        for (int i = 0; i < 2; i++) {
            int o  = i * 256 + tid;             // 512 fragments
            int jm = o >> 5, ln = o & 31;
            int g = ln >> 2, t = ln & 3;
            const float* r = &s[(jm * 8 + g) * 36 + 2 * t];
            uint4 v;
            v.x = packh2(r[0],  r[1]);
            v.y = packh2(r[8],  r[9]);
            v.z = packh2(r[16], r[17]);
            v.w = packh2(r[24], r[25]);
            out[o] = v;
        }
    } else {
        // ---------------- W path ----------------
        __half*  comp = (__half*)smraw;                 // 128 x 18 halves
        uint8_t* metb = (uint8_t*)(smraw + 128 * 18 * 2); // 128 x 8
        const int nb = blockIdx.y - 128;
        const size_t base = ((size_t)nb * 128) * KD + kt * 32;

#pragma unroll
        for (int i = 0; i < 4; i++) {
            int idx = i * 256 + tid;            // 1024 chunks = (row, group)
            int row = idx >> 3;
            int grp = idx & 7;
            size_t off = base + (size_t)row * KD + grp * 4;
            float4 w4 = __ldg((const float4*)(w + off));
            float4 s4 = __ldg((const float4*)(sc + off));
            float4 u4 = __ldg((const float4*)(nu + off));

            float sv[4] = {s4.x, s4.y, s4.z, s4.w};
            float uv[4] = {u4.x, u4.y, u4.z, u4.w};
            float y[4];
#pragma unroll
            for (int j = 0; j < 4; j++)
                y[j] = sv[j] - logf(-logf(uv[j] + EPSV) + EPSV);

            // top-2, first occurrence wins on ties (jax top_k semantics)
            int i1 = 0;
#pragma unroll
            for (int j = 1; j < 4; j++) if (y[j] > y[i1]) i1 = j;
            int i2 = (i1 == 0) ? 1 : 0;
#pragma unroll
            for (int j = 0; j < 4; j++)
                if (j != i1 && j != i2 && y[j] > y[i2]) i2 = j;

            int lo = min(i1, i2), hi = max(i1, i2);
            float wv[4] = {w4.x, w4.y, w4.z, w4.w};
            *(__half2*)&comp[row * 18 + grp * 2] =
                __floats2half2_rn(wv[lo], wv[hi]);
            metb[row * 8 + grp] = (uint8_t)(lo | (hi << 2));
        }
        __syncthreads();

        // A fragments: compressed 16x16 per (jn, k32), dense-m16n8k16 layout
        int jn = tid >> 5, ln = tid & 31;
        int g = ln >> 2, t = ln & 3;
        int r0 = jn * 16 + g, r8 = r0 + 8;
        uint4 v;
        v.x = *(const uint32_t*)&comp[r0 * 18 + 2 * t];
        v.y = *(const uint32_t*)&comp[r8 * 18 + 2 * t];
        v.z = *(const uint32_t*)&comp[r0 * 18 + 2 * t + 8];
        v.w = *(const uint32_t*)&comp[r8 * 18 + 2 * t + 8];
        g_wa[((size_t)nb * NKT + kt) * 256 + tid] = v;

        // metadata: lane%4==0 -> k-groups 0..3, ==1 -> 4..7; low16=row g,
        // high16=row g+8; nibble = idx0 | idx1<<2 (ascending).
        uint32_t e = 0;
        if (t < 2) {
            int gb = t * 4;
            uint32_t lo16 = (uint32_t)metb[r0 * 8 + gb]
                          | ((uint32_t)metb[r0 * 8 + gb + 1] << 4)
                          | ((uint32_t)metb[r0 * 8 + gb + 2] << 8)
                          | ((uint32_t)metb[r0 * 8 + gb + 3] << 12);
            uint32_t hi16 = (uint32_t)metb[r8 * 8 + gb]
                          | ((uint32_t)metb[r8 * 8 + gb + 1] << 4)
                          | ((uint32_t)metb[r8 * 8 + gb + 2] << 8)
                          | ((uint32_t)metb[r8 * 8 + gb + 3] << 12);
            e = lo16 | (hi16 << 16);
        }
        g_we[((size_t)nb * NKT + kt) * 256 + tid] = e;
    }
}

// ------------------------------- GEMM --------------------------------------
// out^T tile: 128 N-rows x 128 M-cols. 8 warps: wn=warp>>1 (32N), wm=warp&1
// (64M). Stage covers K=64 (2 chunks); 64 iterations; 4-stage pipeline.
__global__ void __launch_bounds__(256, 2) gemm_kernel(
    const float* __restrict__ bias,
    float* __restrict__ C)
{
    extern __shared__ char smem[];
    const uint32_t sb = smem_u32(smem);
    const int tid  = threadIdx.x;
    const int warp = tid >> 5;
    const int lane = tid & 31;
    const int wn   = warp >> 1;   // 0..3 -> 32 N rows
    const int wm   = warp & 1;    // 0..1 -> 64 M cols
    const int g    = lane >> 2;
    const int t    = lane & 3;

    const int nb = blockIdx.x;
    const int mb = blockIdx.y;

    const char* pA = (const char*)(g_wa + (size_t)nb * NKT * 256);
    const char* pE = (const char*)(g_we + (size_t)nb * NKT * 256);
    const char* pB = (const char*)(g_xp + (size_t)mb * NKT * 512);

    float acc[2][8][4];
#pragma unroll
    for (int at = 0; at < 2; at++)
#pragma unroll
        for (int bt = 0; bt < 8; bt++)
#pragma unroll
            for (int i = 0; i < 4; i++) acc[at][bt][i] = 0.0f;

    // issue one K=64 stage: A 8KB (2/thr), E 2KB (tid<128), B 16KB (4/thr)
#define ISSUE(st, k2) do {                                                    \
    uint32_t _d = sb + (st) * STAGE_B;                                        \
    size_t _ka = (size_t)(k2) * A_ST;                                         \
    size_t _kb = (size_t)(k2) * B_ST;                                         \
    _Pragma("unroll")                                                         \
    for (int _j = 0; _j < 2; _j++) {                                          \
        int _i = _j * 256 + tid;                                              \
        CP_ASYNC_16(_d + _i * 16, pA + _ka + _i * 16);                        \
    }                                                                         \
    if (tid < 128)                                                            \
        CP_ASYNC_16(_d + A_ST + tid * 16,                                     \
                    pE + (size_t)(k2) * E_ST + tid * 16);                     \
    _Pragma("unroll")                                                         \
    for (int _j = 0; _j < 4; _j++) {                                          \
        int _i = _j * 256 + tid;                                              \
        CP_ASYNC_16(_d + A_ST + E_ST + _i * 16, pB + _kb + _i * 16);          \
    }                                                                         \
    CP_COMMIT();                                                              \
} while (0)

    ISSUE(0, 0);
    ISSUE(1, 1);
    ISSUE(2, 2);

    for (int k2 = 0; k2 < NKT2; k2++) {
        CP_WAIT2();
        __syncthreads();
        if (k2 + 3 < NKT2) ISSUE((k2 + 3) & 3, k2 + 3);

        const char* st = smem + (k2 & 3) * STAGE_B;
#pragma unroll
        for (int kc = 0; kc < 2; kc++) {
            const uint4*    As = (const uint4*)(st + kc * A_CH);
            const uint32_t* Es = (const uint32_t*)(st + A_ST + kc * E_CH);
            const uint4*    Bs = (const uint4*)(st + A_ST + E_ST + kc * B_CH);

            uint4 af[2];
            uint32_t ea[2];
#pragma unroll
            for (int at = 0; at < 2; at++) {
                af[at] = As[(wn * 2 + at) * 32 + lane];
                ea[at] = Es[(wn * 2 + at) * 32 + lane];
            }
#pragma unroll
            for (int bt = 0; bt < 8; bt++) {
                uint4 bf = Bs[(wm * 8 + bt) * 32 + lane];
#pragma unroll
                for (int at = 0; at < 2; at++) {
                    asm volatile(
                        "mma.sp::ordered_metadata.sync.aligned.m16n8k32."
                        "row.col.f32.f16.f16.f32 "
                        "{%0,%1,%2,%3}, {%4,%5,%6,%7}, {%8,%9,%10,%11}, "
                        "{%0,%1,%2,%3}, %12, 0x0;"
                        : "+f"(acc[at][bt][0]), "+f"(acc[at][bt][1]),
                          "+f"(acc[at][bt][2]), "+f"(acc[at][bt][3])
                        : "r"(af[at].x), "r"(af[at].y),
                          "r"(af[at].z), "r"(af[at].w),
                          "r"(bf.x), "r"(bf.y), "r"(bf.z), "r"(bf.w),
                          "r"(ea[at]));
                }
            }
        }
    }
#undef ISSUE

    // ---- epilogue: per-warp smem transpose, coalesced stores + bias ----
    CP_WAIT0();
    __syncthreads();   // wbuf regions overlap stage data other warps may read

    const int n0 = nb * 128 + wn * 32;
    const float bv = __ldg(&bias[n0 + lane]);
    float* wbuf = (float*)(smem + warp * 4224);   // 32 x 33 floats

#pragma unroll
    for (int p = 0; p < 2; p++) {
#pragma unroll
        for (int at = 0; at < 2; at++) {
#pragma unroll
            for (int b2 = 0; b2 < 4; b2++) {
                int bt = p * 4 + b2;
                int mrow = b2 * 8 + 2 * t;
                int ncol = at * 16 + g;
                wbuf[mrow * 33 + ncol]           = acc[at][bt][0];
                wbuf[(mrow + 1) * 33 + ncol]     = acc[at][bt][1];
                wbuf[mrow * 33 + ncol + 8]       = acc[at][bt][2];
                wbuf[(mrow + 1) * 33 + ncol + 8] = acc[at][bt][3];
            }
        }
        __syncwarp();
        long gmr = (long)mb * 128 + wm * 64 + p * 32;
#pragma unroll
        for (int m = 0; m < 32; m++) {
            C[(gmr + m) * (long)ND + n0 + lane] = wbuf[m * 33 + lane] + bv;
        }
        __syncwarp();
    }
}

// ----------------------------- launch --------------------------------------
extern "C" void kernel_launch(void* const* d_in, const int* in_sizes, int n_in,
                              void* d_out, int out_size)
{
    const float* x      = (const float*)d_in[0];
    const float* weight = (const float*)d_in[1];
    const float* bias   = (const float*)d_in[2];
    const float* scores = (const float*)d_in[3];
    const float* noise  = (const float*)d_in[4];
    float* out = (float*)d_out;

    const int M = in_sizes[0] / KD;   // 16384

    cudaFuncSetAttribute(gemm_kernel,
                         cudaFuncAttributeMaxDynamicSharedMemorySize, SMEM_GEMM);

    pack_all<<<dim3(NKT, M / 128 + ND / 128), 256>>>(x, weight, scores, noise);

    dim3 grid(ND / 128, M / 128);     // (nb=32, mb=128), x-fastest shares x-panel
    gemm_kernel<<<grid, 256, SMEM_GEMM>>>(bias, out);
}

// round 14
// speedup vs baseline: 1.1142x; 1.0491x over previous
#include <cuda_runtime.h>
#include <cuda_fp16.h>
#include <cstdint>

// ---------------------------------------------------------------------------
// HDSLinear (sm_103, 2:4 SPARSE HMMA path):
//   out[M,N] = x[M,K] @ (W*mask)[N,K]^T + bias,  M=16384, N=K=4096
// Computed as out^T = Wm @ x^T with mma.sp (A = compressed Wm, 2:4 along K).
// pack_all: fused x-repack + gumbel-mask W-compress (one wave train).
// gemm: CTA tile 128(N) x 128(M), warp tile 64N x 32M (4at x 4bt — balanced,
//       minimizes smem crossbar reads), K-stage depth 64, 4-stage cp.async.cg,
//       mma.sp::ordered_metadata.m16n8k32, 2 CTAs/SM,
//       smem-transpose epilogue with coalesced stores + bias.
// ---------------------------------------------------------------------------

#define EPSV 1e-10f

constexpr int KD = 4096;
constexpr int ND = 4096;
constexpr int NKT = KD / 32;             // 128 k-chunks of 32
constexpr int NKT2 = NKT / 2;            // 64 stages of K=64
constexpr int A_CH = 4096;               // compressed W bytes per k-chunk
constexpr int E_CH = 1024;               // metadata bytes per k-chunk
constexpr int B_CH = 8192;               // x^T bytes per k-chunk
constexpr int A_ST = 2 * A_CH;           // 8192
constexpr int E_ST = 2 * E_CH;           // 2048
constexpr int B_ST = 2 * B_CH;           // 16384
constexpr int STAGE_B = A_ST + E_ST + B_ST;   // 26624
constexpr int SMEM_GEMM = 4 * STAGE_B;        // 106496 (2 CTAs/SM: 208KB)

// fragment panels
__device__ uint4    g_xp[128ull * NKT * 512];   // [mb][kt][jm(16)*32+lane]
__device__ uint4    g_wa[32ull * NKT * 256];    // [nb][kt][jn(8)*32+lane]
__device__ uint32_t g_we[32ull * NKT * 256];    // metadata, same indexing

// ----------------------------- helpers ------------------------------------
__device__ __forceinline__ uint32_t packh2(float lo, float hi) {
    __half2 h = __floats2half2_rn(lo, hi);
    return *(uint32_t*)&h;
}
__device__ __forceinline__ uint32_t smem_u32(const void* p) {
    uint32_t a;
    asm("{ .reg .u64 t; cvta.to.shared.u64 t, %1; cvt.u32.u64 %0, t; }"
        : "=r"(a) : "l"(p));
    return a;
}

#define CP_ASYNC_16(dst, src) \
    asm volatile("cp.async.cg.shared.global [%0], [%1], 16;" \
                 :: "r"(dst), "l"(src) : "memory")
#define CP_COMMIT() asm volatile("cp.async.commit_group;" ::: "memory")
#define CP_WAIT2()  asm volatile("cp.async.wait_group 2;"  ::: "memory")
#define CP_WAIT0()  asm volatile("cp.async.wait_group 0;"  ::: "memory")

// -------------------- pack_all: fused x-repack + W mask/compress ------------
// grid (NKT, 128 + 32), 256 threads.
__global__ void __launch_bounds__(256) pack_all(
    const float* __restrict__ x,
    const float* __restrict__ w,
    const float* __restrict__ sc,
    const float* __restrict__ nu)
{
    __shared__ char smraw[128 * 36 * 4];   // 18432 B, unioned
    const int kt = blockIdx.x, tid = threadIdx.x;

    if (blockIdx.y < 128) {
        // ---------------- x path ----------------
        float* s = (float*)smraw;          // 128 x 36
        const int mb = blockIdx.y;
        const float* xb = x + ((size_t)mb * 128) * KD + kt * 32;

#pragma unroll
        for (int i = 0; i < 4; i++) {
            int idx = i * 256 + tid;
            int row = idx >> 3;
            int c4  = idx & 7;
            float4 v = __ldg((const float4*)(xb + (size_t)row * KD + c4 * 4));
            float* d = &s[row * 36 + c4 * 4];
            d[0] = v.x; d[1] = v.y; d[2] = v.z; d[3] = v.w;
        }
        __syncthreads();

        uint4* out = g_xp + ((size_t)mb * NKT + kt) * 512;
#pragma unroll
        for (int i = 0; i < 2; i++) {
            int o  = i * 256 + tid;             // 512 fragments
            int jm = o >> 5, ln = o & 31;
            int g = ln >> 2, t = ln & 3;
            const float* r = &s[(jm * 8 + g) * 36 + 2 * t];
            uint4 v;
            v.x = packh2(r[0],  r[1]);
            v.y = packh2(r[8],  r[9]);
            v.z = packh2(r[16], r[17]);
            v.w = packh2(r[24], r[25]);
            out[o] = v;
        }
    } else {
        // ---------------- W path ----------------
        __half*  comp = (__half*)smraw;                   // 128 x 18 halves
        uint8_t* metb = (uint8_t*)(smraw + 128 * 18 * 2); // 128 x 8
        const int nb = blockIdx.y - 128;
        const size_t base = ((size_t)nb * 128) * KD + kt * 32;

#pragma unroll
        for (int i = 0; i < 4; i++) {
            int idx = i * 256 + tid;            // 1024 chunks = (row, group)
            int row = idx >> 3;
            int grp = idx & 7;
            size_t off = base + (size_t)row * KD + grp * 4;
            float4 w4 = __ldg((const float4*)(w + off));
            float4 s4 = __ldg((const float4*)(sc + off));
            float4 u4 = __ldg((const float4*)(nu + off));

            float sv[4] = {s4.x, s4.y, s4.z, s4.w};
            float uv[4] = {u4.x, u4.y, u4.z, u4.w};
            float y[4];
#pragma unroll
            for (int j = 0; j < 4; j++)
                y[j] = sv[j] - logf(-logf(uv[j] + EPSV) + EPSV);

            // top-2, first occurrence wins on ties (jax top_k semantics)
            int i1 = 0;
#pragma unroll
            for (int j = 1; j < 4; j++) if (y[j] > y[i1]) i1 = j;
            int i2 = (i1 == 0) ? 1 : 0;
#pragma unroll
            for (int j = 0; j < 4; j++)
                if (j != i1 && j != i2 && y[j] > y[i2]) i2 = j;

            int lo = min(i1, i2), hi = max(i1, i2);
            float wv[4] = {w4.x, w4.y, w4.z, w4.w};
            *(__half2*)&comp[row * 18 + grp * 2] =
                __floats2half2_rn(wv[lo], wv[hi]);
            metb[row * 8 + grp] = (uint8_t)(lo | (hi << 2));
        }
        __syncthreads();

        // A fragments: compressed 16x16 per (jn, k32), dense-m16n8k16 layout
        int jn = tid >> 5, ln = tid & 31;
        int g = ln >> 2, t = ln & 3;
        int r0 = jn * 16 + g, r8 = r0 + 8;
        uint4 v;
        v.x = *(const uint32_t*)&comp[r0 * 18 + 2 * t];
        v.y = *(const uint32_t*)&comp[r8 * 18 + 2 * t];
        v.z = *(const uint32_t*)&comp[r0 * 18 + 2 * t + 8];
        v.w = *(const uint32_t*)&comp[r8 * 18 + 2 * t + 8];
        g_wa[((size_t)nb * NKT + kt) * 256 + tid] = v;

        // metadata: lane%4==0 -> k-groups 0..3, ==1 -> 4..7; low16=row g,
        // high16=row g+8; nibble = idx0 | idx1<<2 (ascending).
        uint32_t e = 0;
        if (t < 2) {
            int gb = t * 4;
            uint32_t lo16 = (uint32_t)metb[r0 * 8 + gb]
                          | ((uint32_t)metb[r0 * 8 + gb + 1] << 4)
                          | ((uint32_t)metb[r0 * 8 + gb + 2] << 8)
                          | ((uint32_t)metb[r0 * 8 + gb + 3] << 12);
            uint32_t hi16 = (uint32_t)metb[r8 * 8 + gb]
                          | ((uint32_t)metb[r8 * 8 + gb + 1] << 4)
                          | ((uint32_t)metb[r8 * 8 + gb + 2] << 8)
                          | ((uint32_t)metb[r8 * 8 + gb + 3] << 12);
            e = lo16 | (hi16 << 16);
        }
        g_we[((size_t)nb * NKT + kt) * 256 + tid] = e;
    }
}

// ------------------------------- GEMM --------------------------------------
// out^T tile: 128 N-rows x 128 M-cols. 8 warps: wm=warp>>1 (4 x 32M),
// wn=warp&1 (2 x 64N). Warp tile 64N x 32M: at=4 A-frags, bt=4 B-frags.
__global__ void __launch_bounds__(256, 2) gemm_kernel(
    const float* __restrict__ bias,
    float* __restrict__ C)
{
    extern __shared__ char smem[];
    const uint32_t sb = smem_u32(smem);
    const int tid  = threadIdx.x;
    const int warp = tid >> 5;
    const int lane = tid & 31;
    const int wm   = warp >> 1;   // 0..3 -> 32 M cols
    const int wn   = warp & 1;    // 0..1 -> 64 N rows
    const int g    = lane >> 2;
    const int t    = lane & 3;

    const int nb = blockIdx.x;
    const int mb = blockIdx.y;

    const char* pA = (const char*)(g_wa + (size_t)nb * NKT * 256);
    const char* pE = (const char*)(g_we + (size_t)nb * NKT * 256);
    const char* pB = (const char*)(g_xp + (size_t)mb * NKT * 512);

    float acc[4][4][4];
#pragma unroll
    for (int at = 0; at < 4; at++)
#pragma unroll
        for (int bt = 0; bt < 4; bt++)
#pragma unroll
            for (int i = 0; i < 4; i++) acc[at][bt][i] = 0.0f;

    // issue one K=64 stage: A 8KB (2/thr), E 2KB (tid<128), B 16KB (4/thr)
#define ISSUE(st, k2) do {                                                    \
    uint32_t _d = sb + (st) * STAGE_B;                                        \
    size_t _ka = (size_t)(k2) * A_ST;                                         \
    size_t _kb = (size_t)(k2) * B_ST;                                         \
    _Pragma("unroll")                                                         \
    for (int _j = 0; _j < 2; _j++) {                                          \
        int _i = _j * 256 + tid;                                              \
        CP_ASYNC_16(_d + _i * 16, pA + _ka + _i * 16);                        \
    }                                                                         \
    if (tid < 128)                                                            \
        CP_ASYNC_16(_d + A_ST + tid * 16,                                     \
                    pE + (size_t)(k2) * E_ST + tid * 16);                     \
    _Pragma("unroll")                                                         \
    for (int _j = 0; _j < 4; _j++) {                                          \
        int _i = _j * 256 + tid;                                              \
        CP_ASYNC_16(_d + A_ST + E_ST + _i * 16, pB + _kb + _i * 16);          \
    }                                                                         \
    CP_COMMIT();                                                              \
} while (0)

    ISSUE(0, 0);
    ISSUE(1, 1);
    ISSUE(2, 2);

    for (int k2 = 0; k2 < NKT2; k2++) {
        CP_WAIT2();
        __syncthreads();
        if (k2 + 3 < NKT2) ISSUE((k2 + 3) & 3, k2 + 3);

        const char* st = smem + (k2 & 3) * STAGE_B;
#pragma unroll
        for (int kc = 0; kc < 2; kc++) {
            const uint4*    As = (const uint4*)(st + kc * A_CH);
            const uint32_t* Es = (const uint32_t*)(st + A_ST + kc * E_CH);
            const uint4*    Bs = (const uint4*)(st + A_ST + E_ST + kc * B_CH);

            uint4 af[4];
            uint32_t ea[4];
#pragma unroll
            for (int at = 0; at < 4; at++) {
                af[at] = As[(wn * 4 + at) * 32 + lane];
                ea[at] = Es[(wn * 4 + at) * 32 + lane];
            }
#pragma unroll
            for (int bt = 0; bt < 4; bt++) {
                uint4 bf = Bs[(wm * 4 + bt) * 32 + lane];
#pragma unroll
                for (int at = 0; at < 4; at++) {
                    asm volatile(
                        "mma.sp::ordered_metadata.sync.aligned.m16n8k32."
                        "row.col.f32.f16.f16.f32 "
                        "{%0,%1,%2,%3}, {%4,%5,%6,%7}, {%8,%9,%10,%11}, "
                        "{%0,%1,%2,%3}, %12, 0x0;"
                        : "+f"(acc[at][bt][0]), "+f"(acc[at][bt][1]),
                          "+f"(acc[at][bt][2]), "+f"(acc[at][bt][3])
                        : "r"(af[at].x), "r"(af[at].y),
                          "r"(af[at].z), "r"(af[at].w),
                          "r"(bf.x), "r"(bf.y), "r"(bf.z), "r"(bf.w),
                          "r"(ea[at]));
                }
            }
        }
    }
#undef ISSUE

    // ---- epilogue: per-warp smem transpose, coalesced stores + bias ----
    // warp region: M rows [mb*128 + wm*32, +32), N cols [nb*128 + wn*64, +64)
    CP_WAIT0();
    __syncthreads();   // wbuf regions overlap stage data other warps may read

    float* wbuf = (float*)(smem + warp * 4224);   // 32 x 33 floats
    const long gm = (long)mb * 128 + wm * 32;

#pragma unroll
    for (int q = 0; q < 2; q++) {                 // N half (32 cols)
        const long n0 = (long)nb * 128 + wn * 64 + q * 32;
        const float bv = __ldg(&bias[n0 + lane]);
#pragma unroll
        for (int a2 = 0; a2 < 2; a2++) {
            int at = q * 2 + a2;
#pragma unroll
            for (int bt = 0; bt < 4; bt++) {
                int mrow = bt * 8 + 2 * t;
                int ncol = a2 * 16 + g;
                wbuf[mrow * 33 + ncol]           = acc[at][bt][0];
                wbuf[(mrow + 1) * 33 + ncol]     = acc[at][bt][1];
                wbuf[mrow * 33 + ncol + 8]       = acc[at][bt][2];
                wbuf[(mrow + 1) * 33 + ncol + 8] = acc[at][bt][3];
            }
        }
        __syncwarp();
#pragma unroll
        for (int m = 0; m < 32; m++) {
            C[(gm + m) * (long)ND + n0 + lane] = wbuf[m * 33 + lane] + bv;
        }
        __syncwarp();
    }
}

// ----------------------------- launch --------------------------------------
extern "C" void kernel_launch(void* const* d_in, const int* in_sizes, int n_in,
                              void* d_out, int out_size)
{
    const float* x      = (const float*)d_in[0];
    const float* weight = (const float*)d_in[1];
    const float* bias   = (const float*)d_in[2];
    const float* scores = (const float*)d_in[3];
    const float* noise  = (const float*)d_in[4];
    float* out = (float*)d_out;

    const int M = in_sizes[0] / KD;   // 16384

    cudaFuncSetAttribute(gemm_kernel,
                         cudaFuncAttributeMaxDynamicSharedMemorySize, SMEM_GEMM);

    pack_all<<<dim3(NKT, M / 128 + ND / 128), 256>>>(x, weight, scores, noise);

    dim3 grid(ND / 128, M / 128);     // (nb=32, mb=128), x-fastest shares x-panel
    gemm_kernel<<<grid, 256, SMEM_GEMM>>>(bias, out);
}